// round 2
// baseline (speedup 1.0000x reference)
#include <cuda_runtime.h>
#include <cstdint>

#define TOK 4096          // B*S tokens
#define DM  4096          // d_model
#define NELEM (TOK * DM)

// Scratch (allocation-free rule: __device__ globals)
__device__ float g_q[NELEM];
__device__ float g_k[NELEM];
__device__ float g_v[NELEM];
__device__ float g_a[NELEM];

__device__ __forceinline__ unsigned f2tf(float f) {
    unsigned u;
    asm("cvt.rna.tf32.f32 %0, %1;" : "=r"(u) : "f"(f));
    return u;
}

__device__ __forceinline__ void ldsm4(unsigned &d0, unsigned &d1, unsigned &d2, unsigned &d3,
                                      const void *p) {
    uint32_t addr = (uint32_t)__cvta_generic_to_shared(p);
    asm volatile("ldmatrix.sync.aligned.m8n8.x4.shared.b16 {%0,%1,%2,%3}, [%4];"
                 : "=r"(d0), "=r"(d1), "=r"(d2), "=r"(d3)
                 : "r"(addr));
}

__device__ __forceinline__ void mma8(float c[4], const unsigned a[4], unsigned b0, unsigned b1) {
    asm volatile("mma.sync.aligned.m16n8k8.row.col.f32.tf32.tf32.f32 "
                 "{%0,%1,%2,%3}, {%4,%5,%6,%7}, {%8,%9}, {%0,%1,%2,%3};"
                 : "+f"(c[0]), "+f"(c[1]), "+f"(c[2]), "+f"(c[3])
                 : "r"(a[0]), "r"(a[1]), "r"(a[2]), "r"(a[3]), "r"(b0), "r"(b1));
}

#define BK 32
#define SK 36   // padded smem stride (36 floats = 144B = odd multiple of 16B -> conflict-free)

// C[M,N] = A[M,K] * W[N,K]^T + bias[N]
// layout==1: row-major C[t*DM + n]
// layout==0: write into (b,h,s,d): ((t/64)*64 + n/64)*4096 + (t%64)*64 + (n%64)
__global__ __launch_bounds__(256, 2) void gemm_tf32(
    const float* __restrict__ A, const float* __restrict__ W,
    const float* __restrict__ bias, float* __restrict__ C, int layout)
{
    __shared__ unsigned As[128][SK];
    __shared__ unsigned Bs[128][SK];

    const int tid  = threadIdx.x;
    const int lane = tid & 31, warp = tid >> 5;
    const int wm = warp >> 1, wn = warp & 1;   // 4x2 warp grid, warp tile 32x64
    const int g  = lane >> 2, tg = lane & 3;
    const int seg = lane >> 3, r8 = lane & 7;
    const int m0 = blockIdx.y * 128, n0 = blockIdx.x * 128;
    const int lc = tid & 7, lr = tid >> 3;     // load mapping: 8 float4-cols x 32 rows

    float acc[2][8][4];
    #pragma unroll
    for (int i = 0; i < 2; i++)
        #pragma unroll
        for (int j = 0; j < 8; j++)
            #pragma unroll
            for (int l = 0; l < 4; l++) acc[i][j][l] = 0.f;

    for (int k0 = 0; k0 < DM; k0 += BK) {
        #pragma unroll
        for (int i = 0; i < 4; i++) {
            int r = lr + i * 32;
            float4 va = *(const float4*)(A + (size_t)(m0 + r) * DM + k0 + lc * 4);
            As[r][lc*4+0] = f2tf(va.x); As[r][lc*4+1] = f2tf(va.y);
            As[r][lc*4+2] = f2tf(va.z); As[r][lc*4+3] = f2tf(va.w);
            float4 vb = *(const float4*)(W + (size_t)(n0 + r) * DM + k0 + lc * 4);
            Bs[r][lc*4+0] = f2tf(vb.x); Bs[r][lc*4+1] = f2tf(vb.y);
            Bs[r][lc*4+2] = f2tf(vb.z); Bs[r][lc*4+3] = f2tf(vb.w);
        }
        __syncthreads();

        #pragma unroll
        for (int ks = 0; ks < BK; ks += 8) {
            unsigned a[2][4], b[4][4];
            #pragma unroll
            for (int mi = 0; mi < 2; mi++) {
                int row = wm * 32 + mi * 16 + (seg & 1) * 8 + r8;
                int col = ks + (seg >> 1) * 4;
                ldsm4(a[mi][0], a[mi][1], a[mi][2], a[mi][3], &As[row][col]);
            }
            #pragma unroll
            for (int nj = 0; nj < 4; nj++) {   // each x4 covers two n8-tiles
                int row = wn * 64 + nj * 16 + (seg >> 1) * 8 + r8;
                int col = ks + (seg & 1) * 4;
                ldsm4(b[nj][0], b[nj][1], b[nj][2], b[nj][3], &Bs[row][col]);
            }
            #pragma unroll
            for (int mi = 0; mi < 2; mi++)
                #pragma unroll
                for (int ni = 0; ni < 8; ni++)
                    mma8(acc[mi][ni], a[mi], b[ni >> 1][(ni & 1) * 2], b[ni >> 1][(ni & 1) * 2 + 1]);
        }
        __syncthreads();
    }

    // Epilogue: bias + layout
    #pragma unroll
    for (int mi = 0; mi < 2; mi++)
        #pragma unroll
        for (int ni = 0; ni < 8; ni++)
            #pragma unroll
            for (int hh = 0; hh < 2; hh++) {
                int row = m0 + wm * 32 + mi * 16 + hh * 8 + g;
                int col = n0 + wn * 64 + ni * 8 + tg * 2;
                float2 v;
                v.x = acc[mi][ni][hh * 2 + 0] + bias[col];
                v.y = acc[mi][ni][hh * 2 + 1] + bias[col + 1];
                size_t idx;
                if (layout)
                    idx = (size_t)row * DM + col;
                else
                    idx = ((size_t)(row >> 6) * 64 + (col >> 6)) * 4096 +
                          (size_t)(row & 63) * 64 + (col & 63);
                *(float2*)(C + idx) = v;
            }
}

// RoPE (faithful to reference's broadcast quirk): angle depends on BATCH index b.
// Pair = adjacent (d even, d odd) within one (b,h,s); m = s*32 + d/2; angle = b * 10000^(-m/2048)
__global__ void rope_kernel(float* __restrict__ q, float* __restrict__ k)
{
    int idx = blockIdx.x * blockDim.x + threadIdx.x;  // pair index, NELEM/2 total
    int dp = idx & 31;
    int s  = (idx >> 5) & 63;
    int b  = idx >> 17;              // 64*64*32 = 2^17 pairs per batch
    int m  = s * 32 + dp;
    float ang = (float)b * exp2f((float)m * (-13.287712379549449f / 2048.0f));
    float sn, cs;
    sincosf(ang, &sn, &cs);
    float2 qa = *(float2*)(q + 2 * (size_t)idx);
    float2 ka = *(float2*)(k + 2 * (size_t)idx);
    float2 qo = { qa.x * cs - qa.y * sn, qa.x * sn + qa.y * cs };
    float2 ko = { ka.x * cs - ka.y * sn, ka.x * sn + ka.y * cs };
    *(float2*)(q + 2 * (size_t)idx) = qo;
    *(float2*)(k + 2 * (size_t)idx) = ko;
}

// One block per (b,h): full 64x64x64 attention in smem/regs (fp32).
// Output written token-major (b,s,h,d) so the final GEMM reads row-major.
__global__ __launch_bounds__(256) void attn_kernel(
    const float* __restrict__ q, const float* __restrict__ k,
    const float* __restrict__ v, float* __restrict__ o)
{
    __shared__ float ps[64][65];   // Q, then P
    __shared__ float ks[64][65];   // K, then V
    const int tid = threadIdx.x;
    const size_t base = (size_t)blockIdx.x * 4096;

    for (int i = tid; i < 4096; i += 256) {
        ps[i >> 6][i & 63] = q[base + i];
        ks[i >> 6][i & 63] = k[base + i];
    }
    __syncthreads();

    const int r = tid >> 2, quad = tid & 3, c0 = quad * 16;
    float s[16];
    #pragma unroll
    for (int j = 0; j < 16; j++) s[j] = 0.f;
    for (int d = 0; d < 64; d++) {
        float qv = ps[r][d];
        #pragma unroll
        for (int j = 0; j < 16; j++) s[j] += qv * ks[c0 + j][d];
    }
    float mx = -1e30f;
    #pragma unroll
    for (int j = 0; j < 16; j++) { s[j] *= 0.125f; mx = fmaxf(mx, s[j]); }
    mx = fmaxf(mx, __shfl_xor_sync(0xffffffffu, mx, 1));
    mx = fmaxf(mx, __shfl_xor_sync(0xffffffffu, mx, 2));
    float sum = 0.f;
    #pragma unroll
    for (int j = 0; j < 16; j++) { s[j] = __expf(s[j] - mx); sum += s[j]; }
    sum += __shfl_xor_sync(0xffffffffu, sum, 1);
    sum += __shfl_xor_sync(0xffffffffu, sum, 2);
    float inv = 1.0f / sum;

    __syncthreads();   // all reads of Q/K done; reuse smem
    #pragma unroll
    for (int j = 0; j < 16; j++) ps[r][c0 + j] = s[j] * inv;
    for (int i = tid; i < 4096; i += 256) ks[i >> 6][i & 63] = v[base + i];
    __syncthreads();

    float oacc[16];
    #pragma unroll
    for (int j = 0; j < 16; j++) oacc[j] = 0.f;
    for (int kk = 0; kk < 64; kk++) {
        float p = ps[r][kk];
        #pragma unroll
        for (int j = 0; j < 16; j++) oacc[j] += p * ks[kk][c0 + j];
    }

    const int bh = blockIdx.x, bb = bh >> 6, h = bh & 63;
    size_t ob = ((size_t)(bb * 64 + r)) * 4096 + h * 64 + c0;  // (b,s,h,d) token-major
    #pragma unroll
    for (int j = 0; j < 16; j++) o[ob + j] = oacc[j];
}

extern "C" void kernel_launch(void* const* d_in, const int* in_sizes, int n_in,
                              void* d_out, int out_size)
{
    const float* x  = (const float*)d_in[0];
    const float* wq = (const float*)d_in[1];
    const float* bq = (const float*)d_in[2];
    const float* wk = (const float*)d_in[3];
    const float* bk = (const float*)d_in[4];
    const float* wv = (const float*)d_in[5];
    const float* bv = (const float*)d_in[6];
    const float* wo = (const float*)d_in[7];
    const float* bo = (const float*)d_in[8];
    float* out = (float*)d_out;

    float *q, *k, *v, *a;
    cudaGetSymbolAddress((void**)&q, g_q);
    cudaGetSymbolAddress((void**)&k, g_k);
    cudaGetSymbolAddress((void**)&v, g_v);
    cudaGetSymbolAddress((void**)&a, g_a);

    dim3 grid(32, 32);
    gemm_tf32<<<grid, 256>>>(x, wq, bq, q, 0);
    gemm_tf32<<<grid, 256>>>(x, wk, bk, k, 0);
    gemm_tf32<<<grid, 256>>>(x, wv, bv, v, 0);
    rope_kernel<<<NELEM / 2 / 256, 256>>>(q, k);
    attn_kernel<<<4096, 256>>>(q, k, v, a);
    gemm_tf32<<<grid, 256>>>(a, wo, bo, out, 1);
}

// round 3
// speedup vs baseline: 1.0946x; 1.0946x over previous
#include <cuda_runtime.h>
#include <cstdint>

#define TOK 4096          // B*S tokens
#define DM  4096          // d_model
#define NELEM (TOK * DM)

// Scratch (allocation-free rule: __device__ globals)
__device__ float g_q[NELEM];
__device__ float g_k[NELEM];
__device__ float g_v[NELEM];
__device__ float g_a[NELEM];

__device__ __forceinline__ unsigned f2tf(float f) {
    unsigned u;
    asm("cvt.rna.tf32.f32 %0, %1;" : "=r"(u) : "f"(f));
    return u;
}

__device__ __forceinline__ void ldsm4(unsigned &d0, unsigned &d1, unsigned &d2, unsigned &d3,
                                      const void *p) {
    uint32_t addr = (uint32_t)__cvta_generic_to_shared(p);
    asm volatile("ldmatrix.sync.aligned.m8n8.x4.shared.b16 {%0,%1,%2,%3}, [%4];"
                 : "=r"(d0), "=r"(d1), "=r"(d2), "=r"(d3)
                 : "r"(addr));
}

__device__ __forceinline__ void mma8(float c[4], const unsigned a[4], unsigned b0, unsigned b1) {
    asm volatile("mma.sync.aligned.m16n8k8.row.col.f32.tf32.tf32.f32 "
                 "{%0,%1,%2,%3}, {%4,%5,%6,%7}, {%8,%9}, {%0,%1,%2,%3};"
                 : "+f"(c[0]), "+f"(c[1]), "+f"(c[2]), "+f"(c[3])
                 : "r"(a[0]), "r"(a[1]), "r"(a[2]), "r"(a[3]), "r"(b0), "r"(b1));
}

__device__ __forceinline__ void cp16(void *smem_dst, const void *gsrc) {
    uint32_t d = (uint32_t)__cvta_generic_to_shared(smem_dst);
    asm volatile("cp.async.cg.shared.global [%0], [%1], 16;\n" :: "r"(d), "l"(gsrc));
}

#define BK 32
#define SK 36   // padded smem stride (36 floats = 144B, 16B-aligned, conflict-free LDSM)
#define STAGE_F (128 * SK)          // floats per matrix per stage
#define SMEM_BYTES (2 * 2 * STAGE_F * 4)   // 2 stages x (A+B) = 73728 B

// C[M,N] = A[M,K] * W[N,K]^T + bias[N]
// layout==1: row-major C[t*DM + n]
// layout==0: write into (b,h,s,d): ((t/64)*64 + n/64)*4096 + (t%64)*64 + (n%64)
__global__ __launch_bounds__(256, 2) void gemm_tf32(
    const float* __restrict__ A, const float* __restrict__ W,
    const float* __restrict__ bias, float* __restrict__ C, int layout)
{
    extern __shared__ float sm[];
    float* As = sm;                  // [2][128][SK] raw fp32
    float* Bs = sm + 2 * STAGE_F;    // [2][128][SK] raw fp32

    const int tid  = threadIdx.x;
    const int lane = tid & 31, warp = tid >> 5;
    const int wm = warp >> 1, wn = warp & 1;   // 4x2 warp grid, warp tile 32x64
    const int g  = lane >> 2, tg = lane & 3;
    const int seg = lane >> 3, r8 = lane & 7;
    const int m0 = blockIdx.y * 128, n0 = blockIdx.x * 128;
    const int lc = tid & 7, lr = tid >> 3;     // load mapping: 8 float4-cols x 32 rows

    float acc[2][8][4];
    #pragma unroll
    for (int i = 0; i < 2; i++)
        #pragma unroll
        for (int j = 0; j < 8; j++)
            #pragma unroll
            for (int l = 0; l < 4; l++) acc[i][j][l] = 0.f;

    // async load of one BK chunk into stage st
    auto loadStage = [&](int kt, int st) {
        const int k0 = kt * BK;
        float* as = As + st * STAGE_F;
        float* bs = Bs + st * STAGE_F;
        #pragma unroll
        for (int i = 0; i < 4; i++) {
            int r = lr + i * 32;
            cp16(&as[r * SK + lc * 4], A + (size_t)(m0 + r) * DM + k0 + lc * 4);
            cp16(&bs[r * SK + lc * 4], W + (size_t)(n0 + r) * DM + k0 + lc * 4);
        }
        asm volatile("cp.async.commit_group;\n");
    };

    const int KT = DM / BK;   // 128
    loadStage(0, 0);

    for (int kt = 0; kt < KT; kt++) {
        const int st = kt & 1;
        asm volatile("cp.async.wait_group 0;\n");
        __syncthreads();                       // stage st visible; prior compute done
        if (kt + 1 < KT) loadStage(kt + 1, st ^ 1);   // overlaps with compute below

        const float* as = As + st * STAGE_F;
        const float* bs = Bs + st * STAGE_F;
        #pragma unroll
        for (int ks = 0; ks < BK; ks += 8) {
            unsigned a[2][4], b[4][4];
            #pragma unroll
            for (int mi = 0; mi < 2; mi++) {
                int row = wm * 32 + mi * 16 + (seg & 1) * 8 + r8;
                int col = ks + (seg >> 1) * 4;
                ldsm4(a[mi][0], a[mi][1], a[mi][2], a[mi][3], &as[row * SK + col]);
            }
            #pragma unroll
            for (int nj = 0; nj < 4; nj++) {   // each x4 covers two n8-tiles
                int row = wn * 64 + nj * 16 + (seg >> 1) * 8 + r8;
                int col = ks + (seg & 1) * 4;
                ldsm4(b[nj][0], b[nj][1], b[nj][2], b[nj][3], &bs[row * SK + col]);
            }
            // tf32 conversion in-register (identical numerics to pre-converted smem)
            #pragma unroll
            for (int mi = 0; mi < 2; mi++)
                #pragma unroll
                for (int l = 0; l < 4; l++) a[mi][l] = f2tf(__uint_as_float(a[mi][l]));
            #pragma unroll
            for (int nj = 0; nj < 4; nj++)
                #pragma unroll
                for (int l = 0; l < 4; l++) b[nj][l] = f2tf(__uint_as_float(b[nj][l]));
            #pragma unroll
            for (int mi = 0; mi < 2; mi++)
                #pragma unroll
                for (int ni = 0; ni < 8; ni++)
                    mma8(acc[mi][ni], a[mi], b[ni >> 1][(ni & 1) * 2], b[ni >> 1][(ni & 1) * 2 + 1]);
        }
    }

    // Epilogue: bias + layout
    #pragma unroll
    for (int mi = 0; mi < 2; mi++)
        #pragma unroll
        for (int ni = 0; ni < 8; ni++)
            #pragma unroll
            for (int hh = 0; hh < 2; hh++) {
                int row = m0 + wm * 32 + mi * 16 + hh * 8 + g;
                int col = n0 + wn * 64 + ni * 8 + tg * 2;
                float2 v;
                v.x = acc[mi][ni][hh * 2 + 0] + bias[col];
                v.y = acc[mi][ni][hh * 2 + 1] + bias[col + 1];
                size_t idx;
                if (layout)
                    idx = (size_t)row * DM + col;
                else
                    idx = ((size_t)(row >> 6) * 64 + (col >> 6)) * 4096 +
                          (size_t)(row & 63) * 64 + (col & 63);
                *(float2*)(C + idx) = v;
            }
}

// RoPE (faithful to reference's broadcast quirk): angle depends on BATCH index b.
// Pair = adjacent (d even, d odd) within one (b,h,s); m = s*32 + d/2; angle = b * 10000^(-m/2048)
__global__ void rope_kernel(float* __restrict__ q, float* __restrict__ k)
{
    int idx = blockIdx.x * blockDim.x + threadIdx.x;  // pair index, NELEM/2 total
    int dp = idx & 31;
    int s  = (idx >> 5) & 63;
    int b  = idx >> 17;              // 64*64*32 = 2^17 pairs per batch
    int m  = s * 32 + dp;
    float ang = (float)b * exp2f((float)m * (-13.287712379549449f / 2048.0f));
    float sn, cs;
    sincosf(ang, &sn, &cs);
    float2 qa = *(float2*)(q + 2 * (size_t)idx);
    float2 ka = *(float2*)(k + 2 * (size_t)idx);
    float2 qo = { qa.x * cs - qa.y * sn, qa.x * sn + qa.y * cs };
    float2 ko = { ka.x * cs - ka.y * sn, ka.x * sn + ka.y * cs };
    *(float2*)(q + 2 * (size_t)idx) = qo;
    *(float2*)(k + 2 * (size_t)idx) = ko;
}

// One block per (b,h): full 64x64x64 attention in smem/regs (fp32).
// Output written token-major (b,s,h,d) so the final GEMM reads row-major.
__global__ __launch_bounds__(256) void attn_kernel(
    const float* __restrict__ q, const float* __restrict__ k,
    const float* __restrict__ v, float* __restrict__ o)
{
    __shared__ float ps[64][65];   // Q, then P
    __shared__ float ks[64][65];   // K, then V
    const int tid = threadIdx.x;
    const size_t base = (size_t)blockIdx.x * 4096;

    for (int i = tid; i < 4096; i += 256) {
        ps[i >> 6][i & 63] = q[base + i];
        ks[i >> 6][i & 63] = k[base + i];
    }
    __syncthreads();

    const int r = tid >> 2, quad = tid & 3, c0 = quad * 16;
    float s[16];
    #pragma unroll
    for (int j = 0; j < 16; j++) s[j] = 0.f;
    for (int d = 0; d < 64; d++) {
        float qv = ps[r][d];
        #pragma unroll
        for (int j = 0; j < 16; j++) s[j] += qv * ks[c0 + j][d];
    }
    float mx = -1e30f;
    #pragma unroll
    for (int j = 0; j < 16; j++) { s[j] *= 0.125f; mx = fmaxf(mx, s[j]); }
    mx = fmaxf(mx, __shfl_xor_sync(0xffffffffu, mx, 1));
    mx = fmaxf(mx, __shfl_xor_sync(0xffffffffu, mx, 2));
    float sum = 0.f;
    #pragma unroll
    for (int j = 0; j < 16; j++) { s[j] = __expf(s[j] - mx); sum += s[j]; }
    sum += __shfl_xor_sync(0xffffffffu, sum, 1);
    sum += __shfl_xor_sync(0xffffffffu, sum, 2);
    float inv = 1.0f / sum;

    __syncthreads();   // all reads of Q/K done; reuse smem
    #pragma unroll
    for (int j = 0; j < 16; j++) ps[r][c0 + j] = s[j] * inv;
    for (int i = tid; i < 4096; i += 256) ks[i >> 6][i & 63] = v[base + i];
    __syncthreads();

    float oacc[16];
    #pragma unroll
    for (int j = 0; j < 16; j++) oacc[j] = 0.f;
    for (int kk = 0; kk < 64; kk++) {
        float p = ps[r][kk];
        #pragma unroll
        for (int j = 0; j < 16; j++) oacc[j] += p * ks[kk][c0 + j];
    }

    const int bh = blockIdx.x, bb = bh >> 6, h = bh & 63;
    size_t ob = ((size_t)(bb * 64 + r)) * 4096 + h * 64 + c0;  // (b,s,h,d) token-major
    #pragma unroll
    for (int j = 0; j < 16; j++) o[ob + j] = oacc[j];
}

extern "C" void kernel_launch(void* const* d_in, const int* in_sizes, int n_in,
                              void* d_out, int out_size)
{
    const float* x  = (const float*)d_in[0];
    const float* wq = (const float*)d_in[1];
    const float* bq = (const float*)d_in[2];
    const float* wk = (const float*)d_in[3];
    const float* bk = (const float*)d_in[4];
    const float* wv = (const float*)d_in[5];
    const float* bv = (const float*)d_in[6];
    const float* wo = (const float*)d_in[7];
    const float* bo = (const float*)d_in[8];
    float* out = (float*)d_out;

    float *q, *k, *v, *a;
    cudaGetSymbolAddress((void**)&q, g_q);
    cudaGetSymbolAddress((void**)&k, g_k);
    cudaGetSymbolAddress((void**)&v, g_v);
    cudaGetSymbolAddress((void**)&a, g_a);

    static int smem_set = 0;
    if (!smem_set) {
        cudaFuncSetAttribute(gemm_tf32, cudaFuncAttributeMaxDynamicSharedMemorySize, SMEM_BYTES);
        smem_set = 1;
    }

    dim3 grid(32, 32);
    gemm_tf32<<<grid, 256, SMEM_BYTES>>>(x, wq, bq, q, 0);
    gemm_tf32<<<grid, 256, SMEM_BYTES>>>(x, wk, bk, k, 0);
    gemm_tf32<<<grid, 256, SMEM_BYTES>>>(x, wv, bv, v, 0);
    rope_kernel<<<NELEM / 2 / 256, 256>>>(q, k);
    attn_kernel<<<4096, 256>>>(q, k, v, a);
    gemm_tf32<<<grid, 256, SMEM_BYTES>>>(a, wo, bo, out, 1);
}

// round 6
// speedup vs baseline: 2.1071x; 1.9250x over previous
#include <cuda_runtime.h>
#include <cuda_fp16.h>
#include <cstdint>

#define DM 4096
#define TOKS 4096
#define NELEM (TOKS * DM)

// Scratch (allocation-free rule: __device__ globals)
__device__ float  g_q[NELEM];
__device__ float  g_k[NELEM];
__device__ float  g_v[NELEM];
__device__ __half g_ah[NELEM];   // attention output (half, token-major)
__device__ __half g_xh[NELEM];   // half activations
__device__ __half g_wh[NELEM];   // half weights (reused per GEMM)

__device__ __forceinline__ void ldsm4(unsigned &d0, unsigned &d1, unsigned &d2, unsigned &d3,
                                      const void *p) {
    uint32_t addr = (uint32_t)__cvta_generic_to_shared(p);
    asm volatile("ldmatrix.sync.aligned.m8n8.x4.shared.b16 {%0,%1,%2,%3}, [%4];"
                 : "=r"(d0), "=r"(d1), "=r"(d2), "=r"(d3)
                 : "r"(addr));
}

__device__ __forceinline__ void mma16(float c[4], const unsigned a[4], unsigned b0, unsigned b1) {
    asm volatile("mma.sync.aligned.m16n8k16.row.col.f32.f16.f16.f32 "
                 "{%0,%1,%2,%3}, {%4,%5,%6,%7}, {%8,%9}, {%0,%1,%2,%3};"
                 : "+f"(c[0]), "+f"(c[1]), "+f"(c[2]), "+f"(c[3])
                 : "r"(a[0]), "r"(a[1]), "r"(a[2]), "r"(a[3]), "r"(b0), "r"(b1));
}

__device__ __forceinline__ void cp16(void *smem_dst, const void *gsrc) {
    uint32_t d = (uint32_t)__cvta_generic_to_shared(smem_dst);
    asm volatile("cp.async.cg.shared.global [%0], [%1], 16;\n" :: "r"(d), "l"(gsrc));
}

// ---------------- fp16 tensor-core GEMM ----------------
// C[M,N] = A[M,K] * W[N,K]^T + bias[N], A/W half, C float.
// layout 1: row-major C. layout 0: scatter to (b,h,s,d); rope!=0 fuses RoPE.
#define BM 128
#define BN 128
#define BK 64
#define SKH 72                        // halves per smem row (144B stride, conflict-free)
#define STG_H (BM * SKH)              // halves per matrix per stage
#define NSTAGE 3
#define GEMM_SMEM (NSTAGE * 2 * STG_H * 2)   // 110592 B

__global__ __launch_bounds__(256, 2) void gemm_fp16(
    const __half* __restrict__ A, const __half* __restrict__ W,
    const float* __restrict__ bias, float* __restrict__ C,
    int layout, int rope)
{
    extern __shared__ __half sm[];
    __half* As = sm;                      // [NSTAGE][BM][SKH]
    __half* Bs = sm + NSTAGE * STG_H;     // [NSTAGE][BN][SKH]

    const int tid  = threadIdx.x;
    const int lane = tid & 31, warp = tid >> 5;
    const int wm = warp >> 1, wn = warp & 1;       // 4x2 warps, warp tile 32x64
    const int g  = lane >> 2, tg = lane & 3;
    const int seg = lane >> 3, r8 = lane & 7;
    const int m0 = blockIdx.y * BM, n0 = blockIdx.x * BN;
    const int lc = tid & 7, lr = tid >> 3;         // 8 chunks x 32 rows per pass

    float acc[2][8][4];
    #pragma unroll
    for (int i = 0; i < 2; i++)
        #pragma unroll
        for (int j = 0; j < 8; j++)
            #pragma unroll
            for (int l = 0; l < 4; l++) acc[i][j][l] = 0.f;

    auto load_stage = [&](int kt) {
        const int st = kt % NSTAGE;
        const int k0 = kt * BK;
        __half* as = As + st * STG_H;
        __half* bs = Bs + st * STG_H;
        #pragma unroll
        for (int i = 0; i < 4; i++) {
            int r = lr + i * 32;
            cp16(&as[r * SKH + lc * 8], A + (size_t)(m0 + r) * DM + k0 + lc * 8);
            cp16(&bs[r * SKH + lc * 8], W + (size_t)(n0 + r) * DM + k0 + lc * 8);
        }
        asm volatile("cp.async.commit_group;\n");
    };

    const int KT = DM / BK;    // 64
    load_stage(0);
    load_stage(1);

    for (int kt = 0; kt < KT; kt++) {
        const int st = kt % NSTAGE;
        asm volatile("cp.async.wait_group 1;\n");
        __syncthreads();                           // stage st ready; prior compute done
        if (kt + 2 < KT) load_stage(kt + 2);       // overlaps with compute below

        const __half* as = As + st * STG_H;
        const __half* bs = Bs + st * STG_H;
        #pragma unroll
        for (int ks = 0; ks < BK / 16; ks++) {     // 4 k16 steps
            unsigned a[2][4], b[4][4];
            #pragma unroll
            for (int mi = 0; mi < 2; mi++) {
                int row = wm * 32 + mi * 16 + (seg & 1) * 8 + r8;
                int col = ks * 16 + (seg >> 1) * 8;
                ldsm4(a[mi][0], a[mi][1], a[mi][2], a[mi][3], &as[row * SKH + col]);
            }
            #pragma unroll
            for (int nj = 0; nj < 4; nj++) {       // each x4: two n8 tiles of k16
                int row = wn * 64 + nj * 16 + (seg >> 1) * 8 + r8;
                int col = ks * 16 + (seg & 1) * 8;
                ldsm4(b[nj][0], b[nj][1], b[nj][2], b[nj][3], &bs[row * SKH + col]);
            }
            #pragma unroll
            for (int mi = 0; mi < 2; mi++)
                #pragma unroll
                for (int ni = 0; ni < 8; ni++)
                    mma16(acc[mi][ni], a[mi],
                          b[ni >> 1][(ni & 1) * 2], b[ni >> 1][(ni & 1) * 2 + 1]);
        }
    }

    // Epilogue: bias (+ optional fused RoPE) + layout
    #pragma unroll
    for (int mi = 0; mi < 2; mi++)
        #pragma unroll
        for (int ni = 0; ni < 8; ni++)
            #pragma unroll
            for (int hh = 0; hh < 2; hh++) {
                int row = m0 + wm * 32 + mi * 16 + hh * 8 + g;
                int col = n0 + wn * 64 + ni * 8 + tg * 2;
                float vx = acc[mi][ni][hh * 2 + 0] + bias[col];
                float vy = acc[mi][ni][hh * 2 + 1] + bias[col + 1];
                if (rope) {
                    // reference quirk: angle depends on BATCH index; m = s*32 + (d%64)/2
                    int bb = row >> 6, ss = row & 63;
                    int m = ss * 32 + ((col & 63) >> 1);
                    float ang = (float)bb * exp2f((float)m * (-13.287712379549449f / 2048.0f));
                    float sn, cs;
                    sincosf(ang, &sn, &cs);
                    float rx = vx * cs - vy * sn, ry = vx * sn + vy * cs;
                    vx = rx; vy = ry;
                }
                size_t idx = layout
                    ? (size_t)row * DM + col
                    : ((size_t)(row >> 6) * 64 + (col >> 6)) * 4096 +
                      (size_t)(row & 63) * 64 + (col & 63);
                *(float2*)(C + idx) = make_float2(vx, vy);
            }
}

// ---------------- fp32 -> fp16 conversion ----------------
__global__ void cvt_h(const float4* __restrict__ in, uint2* __restrict__ out)
{
    size_t i = (size_t)blockIdx.x * blockDim.x + threadIdx.x;
    float4 v = in[i];
    __half2 lo = __floats2half2_rn(v.x, v.y);
    __half2 hi = __floats2half2_rn(v.z, v.w);
    out[i] = make_uint2(*(unsigned*)&lo, *(unsigned*)&hi);
}

// ---------------- attention: one block per (b,h), fp32 math, half output ----------------
__global__ __launch_bounds__(256) void attn_kernel(
    const float* __restrict__ q, const float* __restrict__ k,
    const float* __restrict__ v, __half* __restrict__ o)
{
    __shared__ float ps[64][65];   // Q, then P
    __shared__ float ks[64][65];   // K, then V
    const int tid = threadIdx.x;
    const size_t base = (size_t)blockIdx.x * 4096;

    for (int i = tid; i < 4096; i += 256) {
        ps[i >> 6][i & 63] = q[base + i];
        ks[i >> 6][i & 63] = k[base + i];
    }
    __syncthreads();

    const int r = tid >> 2, quad = tid & 3, c0 = quad * 16;
    float s[16];
    #pragma unroll
    for (int j = 0; j < 16; j++) s[j] = 0.f;
    for (int d = 0; d < 64; d++) {
        float qv = ps[r][d];
        #pragma unroll
        for (int j = 0; j < 16; j++) s[j] += qv * ks[c0 + j][d];
    }
    float mx = -1e30f;
    #pragma unroll
    for (int j = 0; j < 16; j++) { s[j] *= 0.125f; mx = fmaxf(mx, s[j]); }
    mx = fmaxf(mx, __shfl_xor_sync(0xffffffffu, mx, 1));
    mx = fmaxf(mx, __shfl_xor_sync(0xffffffffu, mx, 2));
    float sum = 0.f;
    #pragma unroll
    for (int j = 0; j < 16; j++) { s[j] = __expf(s[j] - mx); sum += s[j]; }
    sum += __shfl_xor_sync(0xffffffffu, sum, 1);
    sum += __shfl_xor_sync(0xffffffffu, sum, 2);
    float inv = 1.0f / sum;

    __syncthreads();
    #pragma unroll
    for (int j = 0; j < 16; j++) ps[r][c0 + j] = s[j] * inv;
    for (int i = tid; i < 4096; i += 256) ks[i >> 6][i & 63] = v[base + i];
    __syncthreads();

    float oacc[16];
    #pragma unroll
    for (int j = 0; j < 16; j++) oacc[j] = 0.f;
    for (int kk = 0; kk < 64; kk++) {
        float p = ps[r][kk];
        #pragma unroll
        for (int j = 0; j < 16; j++) oacc[j] += p * ks[kk][c0 + j];
    }

    const int bh = blockIdx.x, bb = bh >> 6, h = bh & 63;
    size_t ob = ((size_t)(bb * 64 + r)) * 4096 + h * 64 + c0;  // (b,s,h,d) token-major
    #pragma unroll
    for (int j = 0; j < 16; j++) o[ob + j] = __float2half_rn(oacc[j]);
}

extern "C" void kernel_launch(void* const* d_in, const int* in_sizes, int n_in,
                              void* d_out, int out_size)
{
    const float* x  = (const float*)d_in[0];
    const float* wq = (const float*)d_in[1];
    const float* bq = (const float*)d_in[2];
    const float* wk = (const float*)d_in[3];
    const float* bk = (const float*)d_in[4];
    const float* wv = (const float*)d_in[5];
    const float* bv = (const float*)d_in[6];
    const float* wo = (const float*)d_in[7];
    const float* bo = (const float*)d_in[8];
    float* out = (float*)d_out;

    float *q, *k, *v;
    __half *ah, *xh, *wh;
    cudaGetSymbolAddress((void**)&q,  g_q);
    cudaGetSymbolAddress((void**)&k,  g_k);
    cudaGetSymbolAddress((void**)&v,  g_v);
    cudaGetSymbolAddress((void**)&ah, g_ah);
    cudaGetSymbolAddress((void**)&xh, g_xh);
    cudaGetSymbolAddress((void**)&wh, g_wh);

    cudaFuncSetAttribute(gemm_fp16, cudaFuncAttributeMaxDynamicSharedMemorySize, GEMM_SMEM);

    const int CVG = NELEM / 4 / 256;   // 16384
    dim3 gg(DM / BN, TOKS / BM);       // (32, 32)

    cvt_h<<<CVG, 256>>>((const float4*)x,  (uint2*)xh);
    cvt_h<<<CVG, 256>>>((const float4*)wq, (uint2*)wh);
    gemm_fp16<<<gg, 256, GEMM_SMEM>>>(xh, wh, bq, q, 0, 1);
    cvt_h<<<CVG, 256>>>((const float4*)wk, (uint2*)wh);
    gemm_fp16<<<gg, 256, GEMM_SMEM>>>(xh, wh, bk, k, 0, 1);
    cvt_h<<<CVG, 256>>>((const float4*)wv, (uint2*)wh);
    gemm_fp16<<<gg, 256, GEMM_SMEM>>>(xh, wh, bv, v, 0, 0);
    attn_kernel<<<4096, 256>>>(q, k, v, ah);
    cvt_h<<<CVG, 256>>>((const float4*)wo, (uint2*)wh);
    gemm_fp16<<<gg, 256, GEMM_SMEM>>>(ah, wh, bo, out, 1, 0);
}